// round 4
// baseline (speedup 1.0000x reference)
#include <cuda_runtime.h>
#include <math.h>

#define D        256
#define CDIM     300
#define N_CFG    50000
#define N_AST    200000
#define N_TEST   1000

#define E_CC 200000
#define E_AA 400000
#define E_AC 200000
#define E_CA 200000
#define E_CT 50000
#define E_TC 50000

// ---------------- static device scratch (no allocations allowed) ----------------
__device__ float g_Xc[(size_t)N_CFG * D];
__device__ float g_Yc[(size_t)N_CFG * D];
__device__ float g_Xa[(size_t)N_AST * D];
__device__ float g_Ya[(size_t)N_AST * D];
__device__ float g_Xt[(size_t)N_TEST * D];
__device__ float g_Yt[(size_t)N_TEST * D];
__device__ float g_AGG[(size_t)N_AST * D];

__device__ int g_cnt[N_AST];
__device__ int g_cur[N_AST];
__device__ int g_off_cc[N_CFG + 1];
__device__ int g_off_aa[N_AST + 1];
__device__ int g_off_ac[N_CFG + 1];
__device__ int g_off_ca[N_AST + 1];
__device__ int g_off_ct[N_TEST + 1];
__device__ int g_off_tc[N_CFG + 1];
__device__ int g_src_cc[E_CC];
__device__ int g_src_aa[E_AA];
__device__ int g_src_ac[E_AC];
__device__ int g_src_ca[E_CA];
__device__ int g_src_ct[E_CT];
__device__ int g_src_tc[E_TC];

// ---------------- CSR build ----------------
__global__ void zero_kernel(int* __restrict__ p, int n) {
    int i = blockIdx.x * 256 + threadIdx.x;
    if (i < n) p[i] = 0;
}

__global__ void hist_kernel(const int* __restrict__ dst, int* __restrict__ cnt, int E) {
    int i = blockIdx.x * 256 + threadIdx.x;
    if (i < E) atomicAdd(&cnt[dst[i]], 1);
}

// single-block exclusive scan: off[i] = sum cnt[0..i-1], off[n] = total
__global__ void scan_kernel(const int* __restrict__ cnt, int* __restrict__ off, int n) {
    __shared__ int ss[1024];
    int t = threadIdx.x;
    int chunk = (n + 1023) >> 10;
    int s0 = t * chunk;
    int s1 = s0 + chunk; if (s1 > n) s1 = n;
    int s = 0;
    for (int i = s0; i < s1; i++) s += cnt[i];
    ss[t] = s;
    __syncthreads();
    for (int o = 1; o < 1024; o <<= 1) {
        int v = (t >= o) ? ss[t - o] : 0;
        __syncthreads();
        ss[t] += v;
        __syncthreads();
    }
    int prefix = (t == 0) ? 0 : ss[t - 1];
    for (int i = s0; i < s1; i++) { off[i] = prefix; prefix += cnt[i]; }
    if (t == 1023) off[n] = ss[1023];
}

__global__ void copy_kernel(const int* __restrict__ a, int* __restrict__ b, int n) {
    int i = blockIdx.x * 256 + threadIdx.x;
    if (i < n) b[i] = a[i];
}

__global__ void place_kernel(const int* __restrict__ e, int E, int* __restrict__ cur,
                             int* __restrict__ srcs) {
    int i = blockIdx.x * 256 + threadIdx.x;
    if (i < E) {
        int s = e[i];
        int d = e[E + i];
        int pos = atomicAdd(&cur[d], 1);
        srcs[pos] = s;
    }
}

// ---------------- encode: concat(lbl_emb[label], content @ W + b) ----------------
// 16 nodes per block, 128 threads: tx(0..31) -> 4 cols, ty(0..3) -> 4 nodes
__global__ __launch_bounds__(128) void encode_kernel(
    const float* __restrict__ content, const int* __restrict__ labels,
    const float* __restrict__ lbl_emb, const float* __restrict__ encW,
    const float* __restrict__ encb, float* __restrict__ out, int n) {
    __shared__ float sh[16 * CDIM];
    int nb = blockIdx.x * 16;
    int cnt = n - nb; if (cnt > 16) cnt = 16;
    int tid = threadIdx.x;
    int total = cnt * CDIM;
    for (int i = tid; i < total; i += 128) sh[i] = content[(size_t)nb * CDIM + i];
    __syncthreads();
    int tx = tid & 31, ty = tid >> 5;
    float acc[4][4];
#pragma unroll
    for (int i = 0; i < 4; i++)
#pragma unroll
        for (int c = 0; c < 4; c++) acc[i][c] = 0.f;

    for (int k = 0; k < CDIM; k += 4) {
        float wv[4][4];
#pragma unroll
        for (int kk = 0; kk < 4; kk++) {
            float4 t4 = *(const float4*)(encW + (size_t)(k + kk) * 128 + tx * 4);
            wv[kk][0] = t4.x; wv[kk][1] = t4.y; wv[kk][2] = t4.z; wv[kk][3] = t4.w;
        }
#pragma unroll
        for (int i = 0; i < 4; i++) {
            float4 a4 = *(const float4*)(sh + (ty * 4 + i) * CDIM + k);
            float av[4] = {a4.x, a4.y, a4.z, a4.w};
#pragma unroll
            for (int kk = 0; kk < 4; kk++)
#pragma unroll
                for (int c = 0; c < 4; c++) acc[i][c] += av[kk] * wv[kk][c];
        }
    }
#pragma unroll
    for (int i = 0; i < 4; i++) {
        int node = nb + ty * 4 + i;
        if (node < n) {
            int lbl = labels[node];
#pragma unroll
            for (int c = 0; c < 4; c++) {
                int col = tx * 4 + c;
                out[(size_t)node * D + 128 + col] = acc[i][c] + encb[col];
                out[(size_t)node * D + col] = lbl_emb[(size_t)lbl * 128 + col];
            }
        }
    }
}

__global__ void test_init_kernel(const float* __restrict__ t_emb, float* __restrict__ out) {
    int i = blockIdx.x * 256 + threadIdx.x;
    if (i < N_TEST * D) out[i] = t_emb[i & 255];
}

// ---------------- bias init: new[d] = sum of b_rel rows targeting type d ----------------
__global__ void bias_init_kernel(float* __restrict__ buf, size_t total,
                                 const float* __restrict__ bl, int r0, int r1, int r2) {
    size_t i = (size_t)blockIdx.x * 256 + threadIdx.x;
    if (i >= total) return;
    int j = (int)(i & 255);
    float v = bl[r0 * D + j];
    if (r1 >= 0) v += bl[r1 * D + j];
    if (r2 >= 0) v += bl[r2 * D + j];
    buf[i] = v;
}

// ---------------- aggregation: agg[d] = sum_{edges -> d} h[src], warp per dst ----------------
__global__ __launch_bounds__(256) void agg_kernel(
    const float* __restrict__ H, const int* __restrict__ off,
    const int* __restrict__ srcs, float* __restrict__ agg, int n_dst) {
    int w = (blockIdx.x * 256 + threadIdx.x) >> 5;
    int lane = threadIdx.x & 31;
    if (w >= n_dst) return;
    int e0 = off[w], e1 = off[w + 1];
    float4 a0 = make_float4(0.f, 0.f, 0.f, 0.f);
    float4 a1 = make_float4(0.f, 0.f, 0.f, 0.f);
    for (int e = e0; e < e1; e++) {
        const float4* p = (const float4*)(H + (size_t)srcs[e] * D);
        float4 x = p[lane];
        float4 y = p[lane + 32];
        a0.x += x.x; a0.y += x.y; a0.z += x.z; a0.w += x.w;
        a1.x += y.x; a1.y += y.y; a1.z += y.z; a1.w += y.w;
    }
    float4* q = (float4*)(agg + (size_t)w * D);
    q[lane] = a0;
    q[lane + 32] = a1;
}

// ---------------- GEMM accumulate: C[M,256] += A[M,256] @ B[256,256] ----------------
// 128x128 tile, BK=16, 256 threads, 8x8 per thread
__global__ __launch_bounds__(256) void gemm_acc_kernel(
    const float* __restrict__ A, const float* __restrict__ B,
    float* __restrict__ C, int M) {
    __shared__ float As[16][132];
    __shared__ float Bs[16][128];
    const int tid = threadIdx.x;
    const int row0 = blockIdx.x * 128;
    const int col0 = blockIdx.y * 128;
    const int tx = tid & 15;
    const int ty = tid >> 4;
    float acc[8][8];
#pragma unroll
    for (int i = 0; i < 8; i++)
#pragma unroll
        for (int j = 0; j < 8; j++) acc[i][j] = 0.f;

    for (int kt = 0; kt < 256; kt += 16) {
#pragma unroll
        for (int it = 0; it < 2; it++) {
            int idx = tid + it * 256;
            int r = idx >> 2;
            int c4 = (idx & 3) * 4;
            int gr = row0 + r;
            float4 v = make_float4(0.f, 0.f, 0.f, 0.f);
            if (gr < M) v = *(const float4*)(A + (size_t)gr * 256 + kt + c4);
            As[c4 + 0][r] = v.x; As[c4 + 1][r] = v.y;
            As[c4 + 2][r] = v.z; As[c4 + 3][r] = v.w;
        }
#pragma unroll
        for (int it = 0; it < 2; it++) {
            int idx = tid + it * 256;
            int r = idx >> 5;
            int c4 = (idx & 31) * 4;
            float4 v = *(const float4*)(B + (size_t)(kt + r) * 256 + col0 + c4);
            *(float4*)&Bs[r][c4] = v;
        }
        __syncthreads();
#pragma unroll
        for (int k = 0; k < 16; k++) {
            float a[8], b[8];
#pragma unroll
            for (int i = 0; i < 8; i++) a[i] = As[k][ty * 8 + i];
#pragma unroll
            for (int j = 0; j < 8; j++) b[j] = Bs[k][tx * 8 + j];
#pragma unroll
            for (int i = 0; i < 8; i++)
#pragma unroll
                for (int j = 0; j < 8; j++) acc[i][j] += a[i] * b[j];
        }
        __syncthreads();
    }
#pragma unroll
    for (int i = 0; i < 8; i++) {
        int gr = row0 + ty * 8 + i;
        if (gr < M) {
#pragma unroll
            for (int j = 0; j < 8; j += 4) {
                float4* p = (float4*)(C + (size_t)gr * 256 + col0 + tx * 8 + j);
                float4 v = *p;
                v.x += acc[i][j]; v.y += acc[i][j + 1];
                v.z += acc[i][j + 2]; v.w += acc[i][j + 3];
                *p = v;
            }
        }
    }
}

// ---------------- relu (+ optional residual) ----------------
__global__ void relu_res_kernel(float4* __restrict__ buf, const float4* __restrict__ res,
                                size_t n4) {
    size_t i = (size_t)blockIdx.x * 256 + threadIdx.x;
    if (i >= n4) return;
    float4 v = buf[i];
    v.x = fmaxf(v.x, 0.f); v.y = fmaxf(v.y, 0.f);
    v.z = fmaxf(v.z, 0.f); v.w = fmaxf(v.w, 0.f);
    if (res) {
        float4 r = res[i];
        v.x += r.x; v.y += r.y; v.z += r.z; v.w += r.w;
    }
    buf[i] = v;
}

// ---------------- decoder + softmax, warp per node ----------------
template <int NO>
__global__ __launch_bounds__(256) void decode_kernel(
    const float* __restrict__ H, const float* __restrict__ W, const float* __restrict__ b,
    float* __restrict__ logits, float* __restrict__ probs, int n) {
    int w = (blockIdx.x * 256 + threadIdx.x) >> 5;
    int lane = threadIdx.x & 31;
    if (w >= n) return;
    const float* h = H + (size_t)w * D;
    float acc[NO];
#pragma unroll
    for (int o = 0; o < NO; o++) acc[o] = 0.f;
#pragma unroll
    for (int jj = 0; jj < 8; jj++) {
        int j = lane + jj * 32;
        float v = h[j];
#pragma unroll
        for (int o = 0; o < NO; o++) acc[o] += v * W[j * NO + o];
    }
#pragma unroll
    for (int s = 16; s > 0; s >>= 1)
#pragma unroll
        for (int o = 0; o < NO; o++) acc[o] += __shfl_xor_sync(0xffffffffu, acc[o], s);
    if (lane == 0) {
        float lg[NO], m = -1e30f;
#pragma unroll
        for (int o = 0; o < NO; o++) { lg[o] = acc[o] + b[o]; m = fmaxf(m, lg[o]); }
        float se = 0.f, ex[NO];
#pragma unroll
        for (int o = 0; o < NO; o++) { ex[o] = expf(lg[o] - m); se += ex[o]; }
        float inv = 1.f / se;
#pragma unroll
        for (int o = 0; o < NO; o++) {
            logits[(size_t)w * NO + o] = lg[o];
            probs[(size_t)w * NO + o] = ex[o] * inv;
        }
    }
}

// ---------------- host orchestration ----------------
extern "C" void kernel_launch(void* const* d_in, const int* in_sizes, int n_in,
                              void* d_out, int out_size) {
    const int*   c_labels  = (const int*)d_in[0];
    const float* c_content = (const float*)d_in[1];
    const int*   a_labels  = (const int*)d_in[2];
    const float* a_content = (const float*)d_in[3];
    const int*   e[6] = {(const int*)d_in[4], (const int*)d_in[5], (const int*)d_in[6],
                         (const int*)d_in[7], (const int*)d_in[8], (const int*)d_in[9]};
    const float* c_lbl_emb = (const float*)d_in[10];
    const float* c_enc_W   = (const float*)d_in[11];
    const float* c_enc_b   = (const float*)d_in[12];
    const float* a_lbl_emb = (const float*)d_in[13];
    const float* a_enc_W   = (const float*)d_in[14];
    const float* a_enc_b   = (const float*)d_in[15];
    const float* t_emb     = (const float*)d_in[16];
    const float* W_rel     = (const float*)d_in[17];
    const float* b_rel     = (const float*)d_in[18];
    const float* dec_W     = (const float*)d_in[19];
    const float* dec_b     = (const float*)d_in[20];
    const float* adec_W    = (const float*)d_in[21];
    const float* adec_b    = (const float*)d_in[22];
    float* out = (float*)d_out;

    float *Xc, *Yc, *Xa, *Ya, *Xt, *Yt, *AGG;
    int *cnt, *cur;
    int *offp[6], *srcp[6];
    cudaGetSymbolAddress((void**)&Xc, g_Xc);
    cudaGetSymbolAddress((void**)&Yc, g_Yc);
    cudaGetSymbolAddress((void**)&Xa, g_Xa);
    cudaGetSymbolAddress((void**)&Ya, g_Ya);
    cudaGetSymbolAddress((void**)&Xt, g_Xt);
    cudaGetSymbolAddress((void**)&Yt, g_Yt);
    cudaGetSymbolAddress((void**)&AGG, g_AGG);
    cudaGetSymbolAddress((void**)&cnt, g_cnt);
    cudaGetSymbolAddress((void**)&cur, g_cur);
    cudaGetSymbolAddress((void**)&offp[0], g_off_cc);
    cudaGetSymbolAddress((void**)&offp[1], g_off_aa);
    cudaGetSymbolAddress((void**)&offp[2], g_off_ac);
    cudaGetSymbolAddress((void**)&offp[3], g_off_ca);
    cudaGetSymbolAddress((void**)&offp[4], g_off_ct);
    cudaGetSymbolAddress((void**)&offp[5], g_off_tc);
    cudaGetSymbolAddress((void**)&srcp[0], g_src_cc);
    cudaGetSymbolAddress((void**)&srcp[1], g_src_aa);
    cudaGetSymbolAddress((void**)&srcp[2], g_src_ac);
    cudaGetSymbolAddress((void**)&srcp[3], g_src_ca);
    cudaGetSymbolAddress((void**)&srcp[4], g_src_ct);
    cudaGetSymbolAddress((void**)&srcp[5], g_src_tc);

    const int En[6]   = {E_CC, E_AA, E_AC, E_CA, E_CT, E_TC};
    const int rsrc[6] = {0, 1, 1, 0, 0, 2};
    const int rdst[6] = {0, 1, 0, 1, 2, 0};
    const int nn[3]   = {N_CFG, N_AST, N_TEST};

    // --- build CSR (dst-bucketed) for all 6 relations ---
    for (int r = 0; r < 6; r++) {
        int nd = nn[rdst[r]];
        int E_ = En[r];
        zero_kernel<<<(nd + 255) / 256, 256>>>(cnt, nd);
        hist_kernel<<<(E_ + 255) / 256, 256>>>(e[r] + E_, cnt, E_);
        scan_kernel<<<1, 1024>>>(cnt, offp[r], nd);
        copy_kernel<<<(nd + 255) / 256, 256>>>(offp[r], cur, nd);
        place_kernel<<<(E_ + 255) / 256, 256>>>(e[r], E_, cur, srcp[r]);
    }

    // --- encode ---
    encode_kernel<<<(N_CFG + 15) / 16, 128>>>(c_content, c_labels, c_lbl_emb,
                                              c_enc_W, c_enc_b, Xc, N_CFG);
    encode_kernel<<<(N_AST + 15) / 16, 128>>>(a_content, a_labels, a_lbl_emb,
                                              a_enc_W, a_enc_b, Xa, N_AST);
    test_init_kernel<<<(N_TEST * D + 255) / 256, 256>>>(t_emb, Xt);

    float* bufs[2][3] = {{Xc, Xa, Xt}, {Yc, Ya, Yt}};

    for (int l = 0; l < 5; l++) {
        float** hin  = bufs[l & 1];
        float** hout = bufs[(l + 1) & 1];
        const float* bl = b_rel + (size_t)l * 6 * D;

        // bias pre-init: cfg <- rels {0,2,5}, ast <- {1,3}, test <- {4}
        {
            size_t tc = (size_t)N_CFG * D, ta = (size_t)N_AST * D, tt = (size_t)N_TEST * D;
            bias_init_kernel<<<(unsigned)((tc + 255) / 256), 256>>>(hout[0], tc, bl, 0, 2, 5);
            bias_init_kernel<<<(unsigned)((ta + 255) / 256), 256>>>(hout[1], ta, bl, 1, 3, -1);
            bias_init_kernel<<<(unsigned)((tt + 255) / 256), 256>>>(hout[2], tt, bl, 4, -1, -1);
        }

        for (int r = 0; r < 6; r++) {
            int nd = nn[rdst[r]];
            agg_kernel<<<(nd + 7) / 8, 256>>>(hin[rsrc[r]], offp[r], srcp[r], AGG, nd);
            dim3 g((nd + 127) / 128, 2);
            gemm_acc_kernel<<<g, 256>>>(AGG, W_rel + ((size_t)l * 6 + r) * D * D,
                                        hout[rdst[r]], nd);
        }

        bool resid = (l == 1) || (l == 3);
        for (int t = 0; t < 3; t++) {
            size_t n4 = (size_t)nn[t] * D / 4;
            relu_res_kernel<<<(unsigned)((n4 + 255) / 256), 256>>>(
                (float4*)hout[t], resid ? (const float4*)hin[t] : (const float4*)nullptr, n4);
        }
    }

    // final h lives in bufs[1] (Y)
    decode_kernel<2><<<(N_CFG + 7) / 8, 256>>>(Yc, dec_W, dec_b,
                                               out, out + (size_t)N_CFG * 2, N_CFG);
    decode_kernel<3><<<(N_AST + 7) / 8, 256>>>(Ya, adec_W, adec_b,
                                               out + (size_t)N_CFG * 4,
                                               out + (size_t)N_CFG * 4 + (size_t)N_AST * 3,
                                               N_AST);
}

// round 17
// speedup vs baseline: 1.5663x; 1.5663x over previous
#include <cuda_runtime.h>
#include <cuda_bf16.h>
#include <math.h>
#include <stdint.h>

#define D        256
#define CDIM     300
#define N_CFG    50000
#define N_AST    200000
#define N_TEST   1000

#define E_CC 200000
#define E_AA 400000
#define E_AC 200000
#define E_CA 200000
#define E_CT 50000
#define E_TC 50000

#define N_WREL (5 * 6 * 256 * 256)

// ---------------- static device scratch (no allocations allowed) ----------------
__device__ float g_Xc[(size_t)N_CFG * D];
__device__ float g_Yc[(size_t)N_CFG * D];
__device__ float g_Xa[(size_t)N_AST * D];
__device__ float g_Ya[(size_t)N_AST * D];
__device__ float g_Xt[(size_t)N_TEST * D];
__device__ float g_Yt[(size_t)N_TEST * D];
__device__ __nv_bfloat16 g_AGGh[(size_t)N_AST * D];
__device__ __nv_bfloat16 g_AGGl[(size_t)N_AST * D];
__device__ __nv_bfloat16 g_Whi[N_WREL];
__device__ __nv_bfloat16 g_Wlo[N_WREL];

__device__ int g_cnt[N_AST];
__device__ int g_cur[N_AST];
__device__ int g_off_cc[N_CFG + 1];
__device__ int g_off_aa[N_AST + 1];
__device__ int g_off_ac[N_CFG + 1];
__device__ int g_off_ca[N_AST + 1];
__device__ int g_off_ct[N_TEST + 1];
__device__ int g_off_tc[N_CFG + 1];
__device__ int g_src_cc[E_CC];
__device__ int g_src_aa[E_AA];
__device__ int g_src_ac[E_AC];
__device__ int g_src_ca[E_CA];
__device__ int g_src_ct[E_CT];
__device__ int g_src_tc[E_TC];

// ---------------- small helpers ----------------
__device__ __forceinline__ void cp16(uint32_t dst, const void* src, int szbytes) {
    asm volatile("cp.async.cg.shared.global [%0], [%1], 16, %2;"
                 :: "r"(dst), "l"(src), "r"(szbytes));
}

__device__ __forceinline__ void mma_bf16(float* d, const uint32_t* a, const uint32_t* b) {
    asm volatile(
        "mma.sync.aligned.m16n8k16.row.col.f32.bf16.bf16.f32 "
        "{%0,%1,%2,%3}, {%4,%5,%6,%7}, {%8,%9}, {%0,%1,%2,%3};"
        : "+f"(d[0]), "+f"(d[1]), "+f"(d[2]), "+f"(d[3])
        : "r"(a[0]), "r"(a[1]), "r"(a[2]), "r"(a[3]), "r"(b[0]), "r"(b[1]));
}

// split two floats into packed bf16x2 hi and lo words
__device__ __forceinline__ void split2(float x, float y, uint32_t& hi, uint32_t& lo) {
    __nv_bfloat16 hx = __float2bfloat16(x);
    __nv_bfloat16 hy = __float2bfloat16(y);
    __nv_bfloat16 lx = __float2bfloat16(x - __bfloat162float(hx));
    __nv_bfloat16 ly = __float2bfloat16(y - __bfloat162float(hy));
    union { __nv_bfloat162 v; uint32_t u; } a, b;
    a.v.x = hx; a.v.y = hy;
    b.v.x = lx; b.v.y = ly;
    hi = a.u; lo = b.u;
}

// ---------------- CSR build ----------------
__global__ void zero_kernel(int* __restrict__ p, int n) {
    int i = blockIdx.x * 256 + threadIdx.x;
    if (i < n) p[i] = 0;
}

__global__ void hist_kernel(const int* __restrict__ dst, int* __restrict__ cnt, int E) {
    int i = blockIdx.x * 256 + threadIdx.x;
    if (i < E) atomicAdd(&cnt[dst[i]], 1);
}

__global__ void scan_kernel(const int* __restrict__ cnt, int* __restrict__ off, int n) {
    __shared__ int ss[1024];
    int t = threadIdx.x;
    int chunk = (n + 1023) >> 10;
    int s0 = t * chunk;
    int s1 = s0 + chunk; if (s1 > n) s1 = n;
    int s = 0;
    for (int i = s0; i < s1; i++) s += cnt[i];
    ss[t] = s;
    __syncthreads();
    for (int o = 1; o < 1024; o <<= 1) {
        int v = (t >= o) ? ss[t - o] : 0;
        __syncthreads();
        ss[t] += v;
        __syncthreads();
    }
    int prefix = (t == 0) ? 0 : ss[t - 1];
    for (int i = s0; i < s1; i++) { off[i] = prefix; prefix += cnt[i]; }
    if (t == 1023) off[n] = ss[1023];
}

__global__ void copy_kernel(const int* __restrict__ a, int* __restrict__ b, int n) {
    int i = blockIdx.x * 256 + threadIdx.x;
    if (i < n) b[i] = a[i];
}

__global__ void place_kernel(const int* __restrict__ e, int E, int* __restrict__ cur,
                             int* __restrict__ srcs) {
    int i = blockIdx.x * 256 + threadIdx.x;
    if (i < E) {
        int s = e[i];
        int d = e[E + i];
        int pos = atomicAdd(&cur[d], 1);
        srcs[pos] = s;
    }
}

// ---------------- split W_rel into bf16 hi/lo, transposed [l][r][n][k] ----------------
__global__ void split_w_kernel(const float* __restrict__ w, __nv_bfloat16* __restrict__ hi,
                               __nv_bfloat16* __restrict__ lo, int n) {
    int i = blockIdx.x * 256 + threadIdx.x;
    if (i >= n) return;
    float v = w[i];
    int base = i & ~65535;
    int kn = i & 65535;
    int k = kn >> 8, nn = kn & 255;
    int dst = base | (nn << 8) | k;
    __nv_bfloat16 h = __float2bfloat16(v);
    hi[dst] = h;
    lo[dst] = __float2bfloat16(v - __bfloat162float(h));
}

// ---------------- encode: concat(lbl_emb[label], content @ W + b) ----------------
__global__ __launch_bounds__(128) void encode_kernel(
    const float* __restrict__ content, const int* __restrict__ labels,
    const float* __restrict__ lbl_emb, const float* __restrict__ encW,
    const float* __restrict__ encb, float* __restrict__ out, int n) {
    __shared__ float sh[16 * CDIM];
    int nb = blockIdx.x * 16;
    int cnt = n - nb; if (cnt > 16) cnt = 16;
    int tid = threadIdx.x;
    int total = cnt * CDIM;
    for (int i = tid; i < total; i += 128) sh[i] = content[(size_t)nb * CDIM + i];
    __syncthreads();
    int tx = tid & 31, ty = tid >> 5;
    float acc[4][4];
#pragma unroll
    for (int i = 0; i < 4; i++)
#pragma unroll
        for (int c = 0; c < 4; c++) acc[i][c] = 0.f;

    for (int k = 0; k < CDIM; k += 4) {
        float wv[4][4];
#pragma unroll
        for (int kk = 0; kk < 4; kk++) {
            float4 t4 = *(const float4*)(encW + (size_t)(k + kk) * 128 + tx * 4);
            wv[kk][0] = t4.x; wv[kk][1] = t4.y; wv[kk][2] = t4.z; wv[kk][3] = t4.w;
        }
#pragma unroll
        for (int i = 0; i < 4; i++) {
            float4 a4 = *(const float4*)(sh + (ty * 4 + i) * CDIM + k);
            float av[4] = {a4.x, a4.y, a4.z, a4.w};
#pragma unroll
            for (int kk = 0; kk < 4; kk++)
#pragma unroll
                for (int c = 0; c < 4; c++) acc[i][c] += av[kk] * wv[kk][c];
        }
    }
#pragma unroll
    for (int i = 0; i < 4; i++) {
        int node = nb + ty * 4 + i;
        if (node < n) {
            int lbl = labels[node];
#pragma unroll
            for (int c = 0; c < 4; c++) {
                int col = tx * 4 + c;
                out[(size_t)node * D + 128 + col] = acc[i][c] + encb[col];
                out[(size_t)node * D + col] = lbl_emb[(size_t)lbl * 128 + col];
            }
        }
    }
}

__global__ void test_init_kernel(const float* __restrict__ t_emb, float* __restrict__ out) {
    int i = blockIdx.x * 256 + threadIdx.x;
    if (i < N_TEST * D) out[i] = t_emb[i & 255];
}

// ---------------- bias init ----------------
__global__ void bias_init_kernel(float* __restrict__ buf, size_t total,
                                 const float* __restrict__ bl, int r0, int r1, int r2) {
    size_t i = (size_t)blockIdx.x * 256 + threadIdx.x;
    if (i >= total) return;
    int j = (int)(i & 255);
    float v = bl[r0 * D + j];
    if (r1 >= 0) v += bl[r1 * D + j];
    if (r2 >= 0) v += bl[r2 * D + j];
    buf[i] = v;
}

// ---------------- aggregation -> bf16 hi/lo split output ----------------
__global__ __launch_bounds__(256) void agg_kernel(
    const float* __restrict__ H, const int* __restrict__ off,
    const int* __restrict__ srcs, __nv_bfloat16* __restrict__ aggh,
    __nv_bfloat16* __restrict__ aggl, int n_dst) {
    int w = (blockIdx.x * 256 + threadIdx.x) >> 5;
    int lane = threadIdx.x & 31;
    if (w >= n_dst) return;
    int e0 = off[w], e1 = off[w + 1];
    float4 a0 = make_float4(0.f, 0.f, 0.f, 0.f);
    float4 a1 = make_float4(0.f, 0.f, 0.f, 0.f);
    for (int e = e0; e < e1; e++) {
        const float4* p = (const float4*)(H + (size_t)srcs[e] * D);
        float4 x = p[lane];
        float4 y = p[lane + 32];
        a0.x += x.x; a0.y += x.y; a0.z += x.z; a0.w += x.w;
        a1.x += y.x; a1.y += y.y; a1.z += y.z; a1.w += y.w;
    }
    uint32_t* qh = (uint32_t*)(aggh + (size_t)w * D);
    uint32_t* ql = (uint32_t*)(aggl + (size_t)w * D);
    uint32_t h, l;
    split2(a0.x, a0.y, h, l); qh[lane * 2] = h;      ql[lane * 2] = l;
    split2(a0.z, a0.w, h, l); qh[lane * 2 + 1] = h;  ql[lane * 2 + 1] = l;
    split2(a1.x, a1.y, h, l); qh[64 + lane * 2] = h;     ql[64 + lane * 2] = l;
    split2(a1.z, a1.w, h, l); qh[64 + lane * 2 + 1] = h; ql[64 + lane * 2 + 1] = l;
}

// ---------------- double-bf16 tensor-core GEMM: C[M,256] += A @ B ----------------
// A = Ahi+Alo [M][256] row-major bf16; B = Bhi+Blo [256 n][256 k] (transposed) bf16.
// D += Ahi*Bhi + Ahi*Blo + Alo*Bhi  (fp32 accum). 128x128 tile, BK=16, double-buffered.
// 8 warps (2x4), 64x32 warp tile. finalize: relu (+ optional residual) after accumulate.
#define SSTR 24
__global__ __launch_bounds__(256) void gemm_bf16x2_kernel(
    const __nv_bfloat16* __restrict__ Ahi, const __nv_bfloat16* __restrict__ Alo,
    const __nv_bfloat16* __restrict__ Bhi, const __nv_bfloat16* __restrict__ Blo,
    float* __restrict__ C, int M, const float* __restrict__ res, int finalize) {
    __shared__ __nv_bfloat16 sAh[2][128 * SSTR], sAl[2][128 * SSTR];
    __shared__ __nv_bfloat16 sBh[2][128 * SSTR], sBl[2][128 * SSTR];
    const int tid = threadIdx.x;
    const int row0 = blockIdx.x * 128;
    const int col0 = blockIdx.y * 128;
    const int warp = tid >> 5, lane = tid & 31;
    const int wm = (warp & 1) * 64;
    const int wn = (warp >> 1) * 32;
    const int r = lane >> 2, c = lane & 3;

    // load mapping: 2 threads per row, 8 bf16 (16B) each
    const int l_row = tid >> 1;            // 0..127
    const int l_kh  = (tid & 1) * 8;       // 0 or 8
    const int ap = (row0 + l_row) < M ? 16 : 0;

    float acc[4][4][4];
#pragma unroll
    for (int i = 0; i < 4; i++)
#pragma unroll
        for (int j = 0; j < 4; j++)
#pragma unroll
            for (int k = 0; k < 4; k++) acc[i][j][k] = 0.f;

#define LOADSTAGE(t_, buf_) do {                                                       \
    size_t aoff_ = (size_t)(row0 + l_row) * 256 + (t_) * 16 + l_kh;                    \
    uint32_t d1_ = (uint32_t)__cvta_generic_to_shared(&sAh[buf_][l_row * SSTR + l_kh]); \
    cp16(d1_, Ahi + aoff_, ap);                                                        \
    uint32_t d2_ = (uint32_t)__cvta_generic_to_shared(&sAl[buf_][l_row * SSTR + l_kh]); \
    cp16(d2_, Alo + aoff_, ap);                                                        \
    size_t boff_ = (size_t)(col0 + l_row) * 256 + (t_) * 16 + l_kh;                    \
    uint32_t d3_ = (uint32_t)__cvta_generic_to_shared(&sBh[buf_][l_row * SSTR + l_kh]); \
    cp16(d3_, Bhi + boff_, 16);                                                        \
    uint32_t d4_ = (uint32_t)__cvta_generic_to_shared(&sBl[buf_][l_row * SSTR + l_kh]); \
    cp16(d4_, Blo + boff_, 16);                                                        \
} while (0)

    LOADSTAGE(0, 0);
    asm volatile("cp.async.commit_group;" ::: "memory");

    for (int t = 0; t < 16; t++) {
        asm volatile("cp.async.wait_group 0;" ::: "memory");
        __syncthreads();
        if (t + 1 < 16) {
            LOADSTAGE(t + 1, (t + 1) & 1);
            asm volatile("cp.async.commit_group;" ::: "memory");
        }
        const __nv_bfloat16* ah_s = sAh[t & 1];
        const __nv_bfloat16* al_s = sAl[t & 1];
        const __nv_bfloat16* bh_s = sBh[t & 1];
        const __nv_bfloat16* bl_s = sBl[t & 1];

        uint32_t bh[4][2], bl[4][2];
#pragma unroll
        for (int nt = 0; nt < 4; nt++) {
            int n = wn + nt * 8 + r;
            bh[nt][0] = *(const uint32_t*)&bh_s[n * SSTR + 2 * c];
            bh[nt][1] = *(const uint32_t*)&bh_s[n * SSTR + 2 * c + 8];
            bl[nt][0] = *(const uint32_t*)&bl_s[n * SSTR + 2 * c];
            bl[nt][1] = *(const uint32_t*)&bl_s[n * SSTR + 2 * c + 8];
        }
#pragma unroll
        for (int mt = 0; mt < 4; mt++) {
            int m = wm + mt * 16 + r;
            uint32_t ah[4], al[4];
            ah[0] = *(const uint32_t*)&ah_s[m * SSTR + 2 * c];
            ah[1] = *(const uint32_t*)&ah_s[(m + 8) * SSTR + 2 * c];
            ah[2] = *(const uint32_t*)&ah_s[m * SSTR + 2 * c + 8];
            ah[3] = *(const uint32_t*)&ah_s[(m + 8) * SSTR + 2 * c + 8];
            al[0] = *(const uint32_t*)&al_s[m * SSTR + 2 * c];
            al[1] = *(const uint32_t*)&al_s[(m + 8) * SSTR + 2 * c];
            al[2] = *(const uint32_t*)&al_s[m * SSTR + 2 * c + 8];
            al[3] = *(const uint32_t*)&al_s[(m + 8) * SSTR + 2 * c + 8];
#pragma unroll
            for (int nt = 0; nt < 4; nt++) {
                mma_bf16(acc[mt][nt], ah, bh[nt]);
                mma_bf16(acc[mt][nt], ah, bl[nt]);
                mma_bf16(acc[mt][nt], al, bh[nt]);
            }
        }
        __syncthreads();
    }
#undef LOADSTAGE

    // epilogue: accumulate into C (+ optional relu/residual finalize)
#pragma unroll
    for (int mt = 0; mt < 4; mt++) {
#pragma unroll
        for (int half = 0; half < 2; half++) {
            int m = row0 + wm + mt * 16 + r + half * 8;
            if (m < M) {
#pragma unroll
                for (int nt = 0; nt < 4; nt++) {
                    int n = col0 + wn + nt * 8 + 2 * c;
                    float2* p = (float2*)(C + (size_t)m * 256 + n);
                    float2 v = *p;
                    v.x += acc[mt][nt][half * 2 + 0];
                    v.y += acc[mt][nt][half * 2 + 1];
                    if (finalize) {
                        v.x = fmaxf(v.x, 0.f);
                        v.y = fmaxf(v.y, 0.f);
                        if (res) {
                            float2 rv = *(const float2*)(res + (size_t)m * 256 + n);
                            v.x += rv.x; v.y += rv.y;
                        }
                    }
                    *p = v;
                }
            }
        }
    }
}

// ---------------- decoder + softmax, warp per node ----------------
template <int NO>
__global__ __launch_bounds__(256) void decode_kernel(
    const float* __restrict__ H, const float* __restrict__ W, const float* __restrict__ b,
    float* __restrict__ logits, float* __restrict__ probs, int n) {
    int w = (blockIdx.x * 256 + threadIdx.x) >> 5;
    int lane = threadIdx.x & 31;
    if (w >= n) return;
    const float* h = H + (size_t)w * D;
    float acc[NO];
#pragma unroll
    for (int o = 0; o < NO; o++) acc[o] = 0.f;
#pragma unroll
    for (int jj = 0; jj < 8; jj++) {
        int j = lane + jj * 32;
        float v = h[j];
#pragma unroll
        for (int o = 0; o < NO; o++) acc[o] += v * W[j * NO + o];
    }
#pragma unroll
    for (int s = 16; s > 0; s >>= 1)
#pragma unroll
        for (int o = 0; o < NO; o++) acc[o] += __shfl_xor_sync(0xffffffffu, acc[o], s);
    if (lane == 0) {
        float lg[NO], m = -1e30f;
#pragma unroll
        for (int o = 0; o < NO; o++) { lg[o] = acc[o] + b[o]; m = fmaxf(m, lg[o]); }
        float se = 0.f, ex[NO];
#pragma unroll
        for (int o = 0; o < NO; o++) { ex[o] = expf(lg[o] - m); se += ex[o]; }
        float inv = 1.f / se;
#pragma unroll
        for (int o = 0; o < NO; o++) {
            logits[(size_t)w * NO + o] = lg[o];
            probs[(size_t)w * NO + o] = ex[o] * inv;
        }
    }
}

// ---------------- host orchestration ----------------
extern "C" void kernel_launch(void* const* d_in, const int* in_sizes, int n_in,
                              void* d_out, int out_size) {
    const int*   c_labels  = (const int*)d_in[0];
    const float* c_content = (const float*)d_in[1];
    const int*   a_labels  = (const int*)d_in[2];
    const float* a_content = (const float*)d_in[3];
    const int*   e[6] = {(const int*)d_in[4], (const int*)d_in[5], (const int*)d_in[6],
                         (const int*)d_in[7], (const int*)d_in[8], (const int*)d_in[9]};
    const float* c_lbl_emb = (const float*)d_in[10];
    const float* c_enc_W   = (const float*)d_in[11];
    const float* c_enc_b   = (const float*)d_in[12];
    const float* a_lbl_emb = (const float*)d_in[13];
    const float* a_enc_W   = (const float*)d_in[14];
    const float* a_enc_b   = (const float*)d_in[15];
    const float* t_emb     = (const float*)d_in[16];
    const float* W_rel     = (const float*)d_in[17];
    const float* b_rel     = (const float*)d_in[18];
    const float* dec_W     = (const float*)d_in[19];
    const float* dec_b     = (const float*)d_in[20];
    const float* adec_W    = (const float*)d_in[21];
    const float* adec_b    = (const float*)d_in[22];
    float* out = (float*)d_out;

    float *Xc, *Yc, *Xa, *Ya, *Xt, *Yt;
    __nv_bfloat16 *AGGh, *AGGl, *Whi, *Wlo;
    int *cnt, *cur;
    int *offp[6], *srcp[6];
    cudaGetSymbolAddress((void**)&Xc, g_Xc);
    cudaGetSymbolAddress((void**)&Yc, g_Yc);
    cudaGetSymbolAddress((void**)&Xa, g_Xa);
    cudaGetSymbolAddress((void**)&Ya, g_Ya);
    cudaGetSymbolAddress((void**)&Xt, g_Xt);
    cudaGetSymbolAddress((void**)&Yt, g_Yt);
    cudaGetSymbolAddress((void**)&AGGh, g_AGGh);
    cudaGetSymbolAddress((void**)&AGGl, g_AGGl);
    cudaGetSymbolAddress((void**)&Whi, g_Whi);
    cudaGetSymbolAddress((void**)&Wlo, g_Wlo);
    cudaGetSymbolAddress((void**)&cnt, g_cnt);
    cudaGetSymbolAddress((void**)&cur, g_cur);
    cudaGetSymbolAddress((void**)&offp[0], g_off_cc);
    cudaGetSymbolAddress((void**)&offp[1], g_off_aa);
    cudaGetSymbolAddress((void**)&offp[2], g_off_ac);
    cudaGetSymbolAddress((void**)&offp[3], g_off_ca);
    cudaGetSymbolAddress((void**)&offp[4], g_off_ct);
    cudaGetSymbolAddress((void**)&offp[5], g_off_tc);
    cudaGetSymbolAddress((void**)&srcp[0], g_src_cc);
    cudaGetSymbolAddress((void**)&srcp[1], g_src_aa);
    cudaGetSymbolAddress((void**)&srcp[2], g_src_ac);
    cudaGetSymbolAddress((void**)&srcp[3], g_src_ca);
    cudaGetSymbolAddress((void**)&srcp[4], g_src_ct);
    cudaGetSymbolAddress((void**)&srcp[5], g_src_tc);

    const int En[6]   = {E_CC, E_AA, E_AC, E_CA, E_CT, E_TC};
    const int rsrc[6] = {0, 1, 1, 0, 0, 2};
    const int rdst[6] = {0, 1, 0, 1, 2, 0};
    const int fin[6]  = {0, 0, 0, 1, 1, 1};   // last gemm per dst type: r3->ast, r4->test, r5->cfg
    const int nn[3]   = {N_CFG, N_AST, N_TEST};

    // --- split W_rel into bf16 hi/lo, transposed [n][k] ---
    split_w_kernel<<<(N_WREL + 255) / 256, 256>>>(W_rel, Whi, Wlo, N_WREL);

    // --- build CSR (dst-bucketed) for all 6 relations ---
    for (int r = 0; r < 6; r++) {
        int nd = nn[rdst[r]];
        int E_ = En[r];
        zero_kernel<<<(nd + 255) / 256, 256>>>(cnt, nd);
        hist_kernel<<<(E_ + 255) / 256, 256>>>(e[r] + E_, cnt, E_);
        scan_kernel<<<1, 1024>>>(cnt, offp[r], nd);
        copy_kernel<<<(nd + 255) / 256, 256>>>(offp[r], cur, nd);
        place_kernel<<<(E_ + 255) / 256, 256>>>(e[r], E_, cur, srcp[r]);
    }

    // --- encode ---
    encode_kernel<<<(N_CFG + 15) / 16, 128>>>(c_content, c_labels, c_lbl_emb,
                                              c_enc_W, c_enc_b, Xc, N_CFG);
    encode_kernel<<<(N_AST + 15) / 16, 128>>>(a_content, a_labels, a_lbl_emb,
                                              a_enc_W, a_enc_b, Xa, N_AST);
    test_init_kernel<<<(N_TEST * D + 255) / 256, 256>>>(t_emb, Xt);

    float* bufs[2][3] = {{Xc, Xa, Xt}, {Yc, Ya, Yt}};

    for (int l = 0; l < 5; l++) {
        float** hin  = bufs[l & 1];
        float** hout = bufs[(l + 1) & 1];
        const float* bl = b_rel + (size_t)l * 6 * D;
        bool resid = (l == 1) || (l == 3);

        // bias pre-init: cfg <- rels {0,2,5}, ast <- {1,3}, test <- {4}
        {
            size_t tc = (size_t)N_CFG * D, ta = (size_t)N_AST * D, tt = (size_t)N_TEST * D;
            bias_init_kernel<<<(unsigned)((tc + 255) / 256), 256>>>(hout[0], tc, bl, 0, 2, 5);
            bias_init_kernel<<<(unsigned)((ta + 255) / 256), 256>>>(hout[1], ta, bl, 1, 3, -1);
            bias_init_kernel<<<(unsigned)((tt + 255) / 256), 256>>>(hout[2], tt, bl, 4, -1, -1);
        }

        for (int r = 0; r < 6; r++) {
            int nd = nn[rdst[r]];
            agg_kernel<<<(nd + 7) / 8, 256>>>(hin[rsrc[r]], offp[r], srcp[r],
                                              AGGh, AGGl, nd);
            dim3 g((nd + 127) / 128, 2);
            const float* resp = (fin[r] && resid) ? hin[rdst[r]] : nullptr;
            size_t woff = ((size_t)l * 6 + r) * 65536;
            gemm_bf16x2_kernel<<<g, 256>>>(AGGh, AGGl, Whi + woff, Wlo + woff,
                                           hout[rdst[r]], nd, resp, fin[r]);
        }
    }

    // final h lives in bufs[1] (Y)
    decode_kernel<2><<<(N_CFG + 7) / 8, 256>>>(Yc, dec_W, dec_b,
                                               out, out + (size_t)N_CFG * 2, N_CFG);
    decode_kernel<3><<<(N_AST + 7) / 8, 256>>>(Ya, adec_W, adec_b,
                                               out + (size_t)N_CFG * 4,
                                               out + (size_t)N_CFG * 4 + (size_t)N_AST * 3,
                                               N_AST);
}